// round 6
// baseline (speedup 1.0000x reference)
#include <cuda_runtime.h>
#include <cstdint>

#define MM 2048
#define NODE 64
#define TT 256
#define RB 16
#define NTHREADS 256
#define WROW 72            // padded row stride in floats (288B = 18*16B)

// Scratch (no cudaMalloc allowed): softplus table
__device__ __align__(16) float st_g[TT * NODE];   // 64 KB, st_g[0][:]=1.0 (IN_SCALE)

// ---------------- phase 0: softplus table ----------------
__global__ void k_softplus(const float* __restrict__ ne) {
    int idx = blockIdx.x * blockDim.x + threadIdx.x;
    if (idx >= TT * NODE) return;
    int t = idx >> 6;
    int j = idx & 63;
    float v;
    if (t == 0) {
        v = 1.0f;  // IN_SCALE at t=0
    } else {
        float x = ne[j * TT + t];  // noise_embedding layout (1, NODE, T)
        v = fmaxf(x, 0.0f) + log1pf(expf(-fabsf(x)));  // stable softplus
    }
    st_g[idx] = v;
}

__device__ __forceinline__ void cp_async16(uint32_t dst, const void* src) {
    asm volatile("cp.async.cg.shared.global [%0], [%1], 16;\n" :: "r"(dst), "l"(src));
}
// Blackwell packed fp32x2 FMA: acc += a * b (elementwise on both 32-bit halves)
__device__ __forceinline__ void fma2(unsigned long long& acc,
                                     unsigned long long a, unsigned long long b) {
    asm volatile("fma.rn.f32x2 %0, %1, %2, %0;" : "+l"(acc) : "l"(a), "l"(b));
}
__device__ __forceinline__ unsigned long long pack2(float lo, float hi) {
    unsigned long long r;
    asm("mov.b64 %0, {%1, %2};" : "=l"(r) : "r"(__float_as_uint(lo)), "r"(__float_as_uint(hi)));
    return r;
}
__device__ __forceinline__ float hadd2(unsigned long long v) {
    unsigned int lo, hi;
    asm("mov.b64 {%0, %1}, %2;" : "=r"(lo), "=r"(hi) : "l"(v));
    return __uint_as_float(lo) + __uint_as_float(hi);
}

// ---------------- main: fused 255-step recurrence ----------------
__global__ void __launch_bounds__(NTHREADS, 1)
k_chain(const float* __restrict__ W,
        const float* __restrict__ b,
        const float* __restrict__ eps0,
        const float* __restrict__ eps,
        float* __restrict__ out)
{
    // W double buffer, ORIGINAL (j,k) layout, rows padded to 288B : 2 x 18 KB
    __shared__ float Wsh[2][NODE * WROW];
    // x double buffer, rows padded to 288B : 2 x 4.5 KB
    __shared__ float xs[2][RB * WROW];

    const int tid = threadIdx.x;
    const int w   = tid >> 5;
    const int ln  = tid & 31;
    // Warp shape: 8 rows x 4 col-groups -> W-load dedup 8x, x-load 8 distinct rows
    const int rl  = ln >> 2;              // 0..7
    const int gl  = ln & 3;               // 0..3
    const int r   = (w & 1) * 8 + rl;     // 0..15 : row within CTA tile
    const int g   = (w >> 1) * 4 + gl;    // 0..15 : 4-column group
    const int j0  = g << 2;
    const int m   = blockIdx.x * RB + r;

    float* __restrict__ outx = out;
    float* __restrict__ outm = out + (size_t)MM * NODE * TT;
    float* __restrict__ outs = out + 2 * (size_t)MM * NODE * TT;

    const uint32_t wsh_base = (uint32_t)__cvta_generic_to_shared(&Wsh[0][0]);
    const uint32_t WBUF = (uint32_t)(NODE * WROW * 4);   // bytes per W buffer

    // Prefetch W[1] into buffer 1 (buffer parity == t&1).
    // Chunk f (0..1023): j = f>>4, kc = f&15 ; global 16B chunk = W[t]+j*64+kc*4
    {
        const float* src = W + 4096;
        #pragma unroll
        for (int i = 0; i < 4; i++) {
            int f = tid + i * 256;
            int j = f >> 4, kc = f & 15;
            cp_async16(wsh_base + WBUF + (uint32_t)(j * WROW * 4 + kc * 16),
                       src + j * 64 + kc * 4);
        }
        asm volatile("cp.async.commit_group;\n");
    }

    float xreg[8][4], mreg[8][4];   // 8-step output staging (registers)

    // ---- t = 0: x0 = eps0, m0 = 0 ----
    {
        float4 e0 = *(const float4*)(eps0 + (size_t)m * NODE + j0);
        xreg[0][0] = e0.x; xreg[0][1] = e0.y; xreg[0][2] = e0.z; xreg[0][3] = e0.w;
        mreg[0][0] = 0.f;  mreg[0][1] = 0.f;  mreg[0][2] = 0.f;  mreg[0][3] = 0.f;
        *(float4*)&xs[0][r * WROW + j0] = e0;
    }

    // Prefetch per-step vectors for t=1 (registers)
    float4 bv = *(const float4*)(b + 64 + j0);
    float4 sv = *(const float4*)(st_g + 64 + j0);
    float4 ev = *(const float4*)(eps + (size_t)m * NODE + j0);

    #pragma unroll 1
    for (int t = 1; t < TT; ++t) {
        const int cur = (t - 1) & 1;
        const int nxt = t & 1;

        // 1) W[t] landed. 2) Barrier: retired buffer free, xs[cur] visible.
        asm volatile("cp.async.wait_group 0;\n");
        __syncthreads();
        // 3) Prefetch W[t+1] into the retired buffer (overlaps FMA block).
        if (t + 1 < TT) {
            const float* src = W + (size_t)(t + 1) * 4096;
            uint32_t dstb = wsh_base + (uint32_t)((t + 1) & 1) * WBUF;
            #pragma unroll
            for (int i = 0; i < 4; i++) {
                int f = tid + i * 256;
                int j = f >> 4, kc = f & 15;
                cp_async16(dstb + (uint32_t)(j * WROW * 4 + kc * 16),
                           src + j * 64 + kc * 4);
            }
            asm volatile("cp.async.commit_group;\n");
        }

        // Prefetch per-step vectors for t+1 (clamped; hides DRAM latency)
        const int tp = (t + 1 < TT) ? (t + 1) : t;
        float4 bv_n = *(const float4*)(b + tp * 64 + j0);
        float4 sv_n = *(const float4*)(st_g + tp * 64 + j0);
        float4 ev_n = *(const float4*)(eps + ((size_t)(tp - 1) * MM + m) * NODE + j0);

        // Packed even/odd-k accumulation: acc_j = (b_j + sum_even, sum_odd)
        unsigned long long acc0 = pack2(bv.x, 0.f);
        unsigned long long acc1 = pack2(bv.y, 0.f);
        unsigned long long acc2 = pack2(bv.z, 0.f);
        unsigned long long acc3 = pack2(bv.w, 0.f);

        const float* xrow = &xs[cur][r * WROW];
        const float* wb   = &Wsh[nxt][0];

        #pragma unroll
        for (int kc = 0; kc < 16; ++kc) {
            ulonglong2 xp = *(const ulonglong2*)(xrow + kc * 4);                 // x[4kc..4kc+3]
            ulonglong2 w0 = *(const ulonglong2*)(wb + (j0 + 0) * WROW + kc * 4); // W[j][4kc..+3]
            ulonglong2 w1 = *(const ulonglong2*)(wb + (j0 + 1) * WROW + kc * 4);
            ulonglong2 w2 = *(const ulonglong2*)(wb + (j0 + 2) * WROW + kc * 4);
            ulonglong2 w3 = *(const ulonglong2*)(wb + (j0 + 3) * WROW + kc * 4);
            fma2(acc0, xp.x, w0.x); fma2(acc0, xp.y, w0.y);
            fma2(acc1, xp.x, w1.x); fma2(acc1, xp.y, w1.y);
            fma2(acc2, xp.x, w2.x); fma2(acc2, xp.y, w2.y);
            fma2(acc3, xp.x, w3.x); fma2(acc3, xp.y, w3.y);
        }

        float a0 = hadd2(acc0), a1 = hadd2(acc1), a2 = hadd2(acc2), a3 = hadd2(acc3);
        float x0 = a0 + sv.x * ev.x;
        float x1 = a1 + sv.y * ev.y;
        float x2 = a2 + sv.z * ev.z;
        float x3 = a3 + sv.w * ev.w;

        const int tl = t & 7;
        mreg[tl][0] = a0; mreg[tl][1] = a1; mreg[tl][2] = a2; mreg[tl][3] = a3;
        xreg[tl][0] = x0; xreg[tl][1] = x1; xreg[tl][2] = x2; xreg[tl][3] = x3;

        *(float4*)&xs[nxt][r * WROW + j0] = make_float4(x0, x1, x2, x3);

        bv = bv_n; sv = sv_n; ev = ev_n;

        // ---- flush every 8 steps: reversed, 32B-aligned float4 pairs ----
        if (tl == 7) {
            const int cch   = t >> 3;            // chunk id, 0..31
            const int obase = 248 - 8 * cch;     // out offset of t = 8c+7 .. 8c
            float sreg[8][4];
            #pragma unroll
            for (int u = 0; u < 8; ++u) {
                float4 s4 = *(const float4*)(st_g + (8 * cch + u) * NODE + j0);
                sreg[u][0] = s4.x; sreg[u][1] = s4.y; sreg[u][2] = s4.z; sreg[u][3] = s4.w;
            }
            #pragma unroll
            for (int i = 0; i < 4; ++i) {
                size_t base = ((size_t)m * NODE + j0 + i) * TT + obase;
                *(float4*)(outx + base)     = make_float4(xreg[7][i], xreg[6][i], xreg[5][i], xreg[4][i]);
                *(float4*)(outx + base + 4) = make_float4(xreg[3][i], xreg[2][i], xreg[1][i], xreg[0][i]);
                *(float4*)(outm + base)     = make_float4(mreg[7][i], mreg[6][i], mreg[5][i], mreg[4][i]);
                *(float4*)(outm + base + 4) = make_float4(mreg[3][i], mreg[2][i], mreg[1][i], mreg[0][i]);
                *(float4*)(outs + base)     = make_float4(sreg[7][i], sreg[6][i], sreg[5][i], sreg[4][i]);
                *(float4*)(outs + base + 4) = make_float4(sreg[3][i], sreg[2][i], sreg[1][i], sreg[0][i]);
            }
        }
    }
}

extern "C" void kernel_launch(void* const* d_in, const int* in_sizes, int n_in,
                              void* d_out, int out_size) {
    const float* W    = (const float*)d_in[0];   // (T, NODE, NODE)
    const float* b    = (const float*)d_in[1];   // (T, NODE)
    const float* ne   = (const float*)d_in[2];   // (1, NODE, T)
    const float* eps0 = (const float*)d_in[3];   // (M, NODE)
    const float* eps  = (const float*)d_in[4];   // (T-1, M, NODE)
    float* out = (float*)d_out;                  // [x | m | s], each (M, NODE, T)

    k_softplus<<<(TT * NODE + 255) / 256, 256>>>(ne);
    k_chain<<<MM / RB, NTHREADS>>>(W, b, eps0, eps, out);
}

// round 7
// speedup vs baseline: 1.8372x; 1.8372x over previous
#include <cuda_runtime.h>
#include <cstdint>

#define MM 2048
#define NODE 64
#define TT 256
#define RB 16
#define NTHREADS 256
#define WROW 68            // row stride in floats: 272B, 16B-aligned, banks shift 4/row

// Scratch (no cudaMalloc allowed): softplus table
__device__ __align__(16) float st_g[TT * NODE];   // 64 KB, st_g[0][:]=1.0 (IN_SCALE)

// ---------------- phase 0: softplus table ----------------
__global__ void k_softplus(const float* __restrict__ ne) {
    int idx = blockIdx.x * blockDim.x + threadIdx.x;
    if (idx >= TT * NODE) return;
    int t = idx >> 6;
    int j = idx & 63;
    float v;
    if (t == 0) {
        v = 1.0f;  // IN_SCALE at t=0
    } else {
        float x = ne[j * TT + t];  // noise_embedding layout (1, NODE, T)
        v = fmaxf(x, 0.0f) + log1pf(expf(-fabsf(x)));  // stable softplus
    }
    st_g[idx] = v;
}

__device__ __forceinline__ void cp_async16(uint32_t dst, const void* src) {
    asm volatile("cp.async.cg.shared.global [%0], [%1], 16;\n" :: "r"(dst), "l"(src));
}
// Blackwell packed fp32x2 FMA: acc += a * b (elementwise on both 32-bit halves)
__device__ __forceinline__ void fma2(unsigned long long& acc,
                                     unsigned long long a, unsigned long long b) {
    asm volatile("fma.rn.f32x2 %0, %1, %2, %0;" : "+l"(acc) : "l"(a), "l"(b));
}
__device__ __forceinline__ unsigned long long pack2(float lo, float hi) {
    unsigned long long r;
    asm("mov.b64 %0, {%1, %2};" : "=l"(r) : "r"(__float_as_uint(lo)), "r"(__float_as_uint(hi)));
    return r;
}
__device__ __forceinline__ float hadd2(unsigned long long v) {
    unsigned int lo, hi;
    asm("mov.b64 {%0, %1}, %2;" : "=r"(lo), "=r"(hi) : "l"(v));
    return __uint_as_float(lo) + __uint_as_float(hi);
}

// ---------------- main: fused 255-step recurrence ----------------
__global__ void __launch_bounds__(NTHREADS, 1)
k_chain(const float* __restrict__ W,
        const float* __restrict__ b,
        const float* __restrict__ eps0,
        const float* __restrict__ eps,
        float* __restrict__ out)
{
    // W double buffer, ORIGINAL (j,k) layout, rows padded to 272B : 2 x 17.4 KB
    __shared__ float Wsh[2][NODE * WROW];
    // x double buffer, rows padded to 272B
    __shared__ float xs[2][RB * WROW];

    const int tid = threadIdx.x;
    const int w   = tid >> 5;
    const int ln  = tid & 31;
    const int rl  = ln >> 2;              // 0..7 : row within warp
    const int gl  = ln & 3;               // 0..3 : column phase within span
    const int r   = (w & 1) * 8 + rl;     // 0..15 : row within CTA tile
    const int cb  = (w >> 1) * 16;        // column span base: 0,16,32,48
    const int m   = blockIdx.x * RB + r;
    // This thread's 4 output columns: cb + gl + 4*i  (strided by 4)
    int col[4];
    #pragma unroll
    for (int i = 0; i < 4; ++i) col[i] = cb + gl + 4 * i;

    float* __restrict__ outx = out;
    float* __restrict__ outm = out + (size_t)MM * NODE * TT;
    float* __restrict__ outs = out + 2 * (size_t)MM * NODE * TT;

    const uint32_t wsh_base = (uint32_t)__cvta_generic_to_shared(&Wsh[0][0]);
    const uint32_t WBUF = (uint32_t)(NODE * WROW * 4);   // bytes per W buffer

    // Prefetch W[1] into buffer 1 (buffer parity == t&1).
    // Chunk f (0..1023): j = f>>4, kc = f&15 ; 16B chunk of row j
    {
        const float* src = W + 4096;
        #pragma unroll
        for (int i = 0; i < 4; i++) {
            int f = tid + i * 256;
            int j = f >> 4, kc = f & 15;
            cp_async16(wsh_base + WBUF + (uint32_t)(j * (WROW * 4) + kc * 16),
                       src + j * 64 + kc * 4);
        }
        asm volatile("cp.async.commit_group;\n");
    }

    float xreg[8][4], mreg[8][4];   // 8-step output staging (registers)

    // ---- t = 0: x0 = eps0, m0 = 0 ----
    #pragma unroll
    for (int i = 0; i < 4; ++i) {
        float e0 = eps0[(size_t)m * NODE + col[i]];
        xreg[0][i] = e0;  mreg[0][i] = 0.f;
        xs[0][r * WROW + col[i]] = e0;
    }

    // Prefetch per-step vectors for t=1 (registers, scalar per strided col)
    float bv[4], sv[4], ev[4];
    #pragma unroll
    for (int i = 0; i < 4; ++i) {
        bv[i] = b[64 + col[i]];
        sv[i] = st_g[64 + col[i]];
        ev[i] = eps[(size_t)m * NODE + col[i]];
    }

    #pragma unroll 1
    for (int t = 1; t < TT; ++t) {
        const int cur = (t - 1) & 1;
        const int nxt = t & 1;

        // 1) W[t] landed. 2) Barrier: retired buffer free, xs[cur] visible.
        asm volatile("cp.async.wait_group 0;\n");
        __syncthreads();
        // 3) Prefetch W[t+1] into the retired buffer (overlaps FMA block).
        if (t + 1 < TT) {
            const float* src = W + (size_t)(t + 1) * 4096;
            uint32_t dstb = wsh_base + (uint32_t)((t + 1) & 1) * WBUF;
            #pragma unroll
            for (int i = 0; i < 4; i++) {
                int f = tid + i * 256;
                int j = f >> 4, kc = f & 15;
                cp_async16(dstb + (uint32_t)(j * (WROW * 4) + kc * 16),
                           src + j * 64 + kc * 4);
            }
            asm volatile("cp.async.commit_group;\n");
        }

        // Prefetch per-step vectors for t+1 (hides DRAM latency under FMAs)
        const int tp = (t + 1 < TT) ? (t + 1) : t;
        float bn[4], sn[4], en[4];
        #pragma unroll
        for (int i = 0; i < 4; ++i) {
            bn[i] = b[tp * 64 + col[i]];
            sn[i] = st_g[tp * 64 + col[i]];
            en[i] = eps[((size_t)(tp - 1) * MM + m) * NODE + col[i]];
        }

        // Packed even/odd-k accumulation: acc_i = (b + sum_even_k, sum_odd_k)
        unsigned long long acc0 = pack2(bv[0], 0.f);
        unsigned long long acc1 = pack2(bv[1], 0.f);
        unsigned long long acc2 = pack2(bv[2], 0.f);
        unsigned long long acc3 = pack2(bv[3], 0.f);

        const float* xrow = &xs[cur][r * WROW];
        const float* wb   = &Wsh[nxt][0];
        const float* wr0  = wb + col[0] * WROW;   // rows gl, gl+4, gl+8, gl+12 (+cb)
        const float* wr1  = wb + col[1] * WROW;   // lane deltas {0,1,2,3} rows
        const float* wr2  = wb + col[2] * WROW;   //  -> banks 4*gl apart: conflict-free
        const float* wr3  = wb + col[3] * WROW;

        #pragma unroll
        for (int kc = 0; kc < 16; ++kc) {
            ulonglong2 xp = *(const ulonglong2*)(xrow + kc * 4);  // (x0,x1),(x2,x3)
            ulonglong2 w0 = *(const ulonglong2*)(wr0 + kc * 4);
            ulonglong2 w1 = *(const ulonglong2*)(wr1 + kc * 4);
            ulonglong2 w2 = *(const ulonglong2*)(wr2 + kc * 4);
            ulonglong2 w3 = *(const ulonglong2*)(wr3 + kc * 4);
            fma2(acc0, xp.x, w0.x); fma2(acc0, xp.y, w0.y);
            fma2(acc1, xp.x, w1.x); fma2(acc1, xp.y, w1.y);
            fma2(acc2, xp.x, w2.x); fma2(acc2, xp.y, w2.y);
            fma2(acc3, xp.x, w3.x); fma2(acc3, xp.y, w3.y);
        }

        float a[4] = { hadd2(acc0), hadd2(acc1), hadd2(acc2), hadd2(acc3) };

        const int tl = t & 7;
        #pragma unroll
        for (int i = 0; i < 4; ++i) {
            float xv = a[i] + sv[i] * ev[i];
            mreg[tl][i] = a[i];
            xreg[tl][i] = xv;
            xs[nxt][r * WROW + col[i]] = xv;   // 32 distinct banks across warp
            bv[i] = bn[i]; sv[i] = sn[i]; ev[i] = en[i];
        }

        // ---- flush every 8 steps: reversed, 32B-aligned float4 pairs ----
        if (tl == 7) {
            const int cch   = t >> 3;            // chunk id, 0..31
            const int obase = 248 - 8 * cch;     // out offset of t = 8c+7 .. 8c
            float sreg[8][4];
            #pragma unroll
            for (int u = 0; u < 8; ++u)
                #pragma unroll
                for (int i = 0; i < 4; ++i)
                    sreg[u][i] = st_g[(8 * cch + u) * NODE + col[i]];
            #pragma unroll
            for (int i = 0; i < 4; ++i) {
                size_t base = ((size_t)m * NODE + col[i]) * TT + obase;
                *(float4*)(outx + base)     = make_float4(xreg[7][i], xreg[6][i], xreg[5][i], xreg[4][i]);
                *(float4*)(outx + base + 4) = make_float4(xreg[3][i], xreg[2][i], xreg[1][i], xreg[0][i]);
                *(float4*)(outm + base)     = make_float4(mreg[7][i], mreg[6][i], mreg[5][i], mreg[4][i]);
                *(float4*)(outm + base + 4) = make_float4(mreg[3][i], mreg[2][i], mreg[1][i], mreg[0][i]);
                *(float4*)(outs + base)     = make_float4(sreg[7][i], sreg[6][i], sreg[5][i], sreg[4][i]);
                *(float4*)(outs + base + 4) = make_float4(sreg[3][i], sreg[2][i], sreg[1][i], sreg[0][i]);
            }
        }
    }
}

extern "C" void kernel_launch(void* const* d_in, const int* in_sizes, int n_in,
                              void* d_out, int out_size) {
    const float* W    = (const float*)d_in[0];   // (T, NODE, NODE)
    const float* b    = (const float*)d_in[1];   // (T, NODE)
    const float* ne   = (const float*)d_in[2];   // (1, NODE, T)
    const float* eps0 = (const float*)d_in[3];   // (M, NODE)
    const float* eps  = (const float*)d_in[4];   // (T-1, M, NODE)
    float* out = (float*)d_out;                  // [x | m | s], each (M, NODE, T)

    k_softplus<<<(TT * NODE + 255) / 256, 256>>>(ne);
    k_chain<<<MM / RB, NTHREADS>>>(W, b, eps0, eps, out);
}

// round 8
// speedup vs baseline: 2.0056x; 1.0916x over previous
#include <cuda_runtime.h>
#include <cstdint>

#define MM 2048
#define NODE 64
#define TT 256
#define RB 16
#define NTHREADS 512
#define NC 2               // columns per thread
#define WROW 68            // row stride in floats: 272B, 16B-aligned, banks shift 4/row

// Scratch (no cudaMalloc allowed): softplus table
__device__ __align__(16) float st_g[TT * NODE];   // 64 KB, st_g[0][:]=1.0 (IN_SCALE)

// ---------------- phase 0: softplus table ----------------
__global__ void k_softplus(const float* __restrict__ ne) {
    int idx = blockIdx.x * blockDim.x + threadIdx.x;
    if (idx >= TT * NODE) return;
    int t = idx >> 6;
    int j = idx & 63;
    float v;
    if (t == 0) {
        v = 1.0f;  // IN_SCALE at t=0
    } else {
        float x = ne[j * TT + t];  // noise_embedding layout (1, NODE, T)
        v = fmaxf(x, 0.0f) + log1pf(expf(-fabsf(x)));  // stable softplus
    }
    st_g[idx] = v;
}

__device__ __forceinline__ void cp_async16(uint32_t dst, const void* src) {
    asm volatile("cp.async.cg.shared.global [%0], [%1], 16;\n" :: "r"(dst), "l"(src));
}
// Blackwell packed fp32x2 FMA: acc += a * b (elementwise on both 32-bit halves)
__device__ __forceinline__ void fma2(unsigned long long& acc,
                                     unsigned long long a, unsigned long long b) {
    asm volatile("fma.rn.f32x2 %0, %1, %2, %0;" : "+l"(acc) : "l"(a), "l"(b));
}
__device__ __forceinline__ unsigned long long pack2(float lo, float hi) {
    unsigned long long r;
    asm("mov.b64 %0, {%1, %2};" : "=l"(r) : "r"(__float_as_uint(lo)), "r"(__float_as_uint(hi)));
    return r;
}
__device__ __forceinline__ float hadd2(unsigned long long v) {
    unsigned int lo, hi;
    asm("mov.b64 {%0, %1}, %2;" : "=r"(lo), "=r"(hi) : "l"(v));
    return __uint_as_float(lo) + __uint_as_float(hi);
}

// ---------------- main: fused 255-step recurrence ----------------
__global__ void __launch_bounds__(NTHREADS, 1)
k_chain(const float* __restrict__ W,
        const float* __restrict__ b,
        const float* __restrict__ eps0,
        const float* __restrict__ eps,
        float* __restrict__ out)
{
    // W double buffer, ORIGINAL (j,k) layout, rows padded to 272B : 2 x 17.4 KB
    __shared__ float Wsh[2][NODE * WROW];
    // x double buffer, rows padded to 272B
    __shared__ float xs[2][RB * WROW];

    const int tid = threadIdx.x;
    const int w   = tid >> 5;             // 0..15
    const int ln  = tid & 31;
    const int rl  = ln >> 2;              // 0..7 : row within warp
    const int gl  = ln & 3;               // 0..3 : column phase within span
    const int r   = (w & 1) * 8 + rl;     // 0..15 : row within CTA tile
    const int cb  = (w >> 1) * 8;         // column span base: 0,8,...,56
    const int m   = blockIdx.x * RB + r;
    // This thread's NC output columns: cb + gl + 4*i  (strided by 4)
    int col[NC];
    #pragma unroll
    for (int i = 0; i < NC; ++i) col[i] = cb + gl + 4 * i;

    float* __restrict__ outx = out;
    float* __restrict__ outm = out + (size_t)MM * NODE * TT;
    float* __restrict__ outs = out + 2 * (size_t)MM * NODE * TT;

    const uint32_t wsh_base = (uint32_t)__cvta_generic_to_shared(&Wsh[0][0]);
    const uint32_t WBUF = (uint32_t)(NODE * WROW * 4);   // bytes per W buffer

    // Prefetch W[1] into buffer 1 (buffer parity == t&1).
    // Chunk f (0..1023): j = f>>4, kc = f&15 ; 16B chunk of row j
    {
        const float* src = W + 4096;
        #pragma unroll
        for (int i = 0; i < 2; i++) {
            int f = tid + i * NTHREADS;
            int j = f >> 4, kc = f & 15;
            cp_async16(wsh_base + WBUF + (uint32_t)(j * (WROW * 4) + kc * 16),
                       src + j * 64 + kc * 4);
        }
        asm volatile("cp.async.commit_group;\n");
    }

    float xreg[8][NC], mreg[8][NC];   // 8-step output staging (registers)

    // ---- t = 0: x0 = eps0, m0 = 0 ----
    #pragma unroll
    for (int i = 0; i < NC; ++i) {
        float e0 = eps0[(size_t)m * NODE + col[i]];
        xreg[0][i] = e0;  mreg[0][i] = 0.f;
        xs[0][r * WROW + col[i]] = e0;
    }

    // Prefetch per-step vectors for t=1 (registers, scalar per strided col)
    float bv[NC], sv[NC], ev[NC];
    #pragma unroll
    for (int i = 0; i < NC; ++i) {
        bv[i] = b[64 + col[i]];
        sv[i] = st_g[64 + col[i]];
        ev[i] = __ldcs(eps + (size_t)m * NODE + col[i]);
    }

    #pragma unroll 1
    for (int t = 1; t < TT; ++t) {
        const int cur = (t - 1) & 1;
        const int nxt = t & 1;

        // 1) W[t] landed. 2) Barrier: retired buffer free, xs[cur] visible.
        asm volatile("cp.async.wait_group 0;\n");
        __syncthreads();
        // 3) Prefetch W[t+1] into the retired buffer (overlaps FMA block).
        if (t + 1 < TT) {
            const float* src = W + (size_t)(t + 1) * 4096;
            uint32_t dstb = wsh_base + (uint32_t)((t + 1) & 1) * WBUF;
            #pragma unroll
            for (int i = 0; i < 2; i++) {
                int f = tid + i * NTHREADS;
                int j = f >> 4, kc = f & 15;
                cp_async16(dstb + (uint32_t)(j * (WROW * 4) + kc * 16),
                           src + j * 64 + kc * 4);
            }
            asm volatile("cp.async.commit_group;\n");
        }

        // Prefetch per-step vectors for t+1 (hides DRAM latency under FMAs)
        const int tp = (t + 1 < TT) ? (t + 1) : t;
        float bn[NC], sn[NC], en[NC];
        #pragma unroll
        for (int i = 0; i < NC; ++i) {
            bn[i] = b[tp * 64 + col[i]];
            sn[i] = st_g[tp * 64 + col[i]];
            en[i] = __ldcs(eps + ((size_t)(tp - 1) * MM + m) * NODE + col[i]);
        }

        // Packed even/odd-k accumulation: acc_i = (b + sum_even_k, sum_odd_k)
        unsigned long long acc0 = pack2(bv[0], 0.f);
        unsigned long long acc1 = pack2(bv[1], 0.f);

        const float* xrow = &xs[cur][r * WROW];
        const float* wb   = &Wsh[nxt][0];
        const float* wr0  = wb + col[0] * WROW;   // lane col deltas {0,1,2,3}
        const float* wr1  = wb + col[1] * WROW;   //  -> banks 4*gl apart: conflict-free

        #pragma unroll
        for (int kc = 0; kc < 16; ++kc) {
            ulonglong2 xp = *(const ulonglong2*)(xrow + kc * 4);  // (x0,x1),(x2,x3)
            ulonglong2 w0 = *(const ulonglong2*)(wr0 + kc * 4);
            ulonglong2 w1 = *(const ulonglong2*)(wr1 + kc * 4);
            fma2(acc0, xp.x, w0.x); fma2(acc0, xp.y, w0.y);
            fma2(acc1, xp.x, w1.x); fma2(acc1, xp.y, w1.y);
        }

        float a[NC] = { hadd2(acc0), hadd2(acc1) };

        const int tl = t & 7;
        #pragma unroll
        for (int i = 0; i < NC; ++i) {
            float xv = a[i] + sv[i] * ev[i];
            mreg[tl][i] = a[i];
            xreg[tl][i] = xv;
            xs[nxt][r * WROW + col[i]] = xv;   // 32 distinct banks across warp
            bv[i] = bn[i]; sv[i] = sn[i]; ev[i] = en[i];
        }

        // ---- flush every 8 steps: reversed, 32B-aligned float4 pairs ----
        if (tl == 7) {
            const int cch   = t >> 3;            // chunk id, 0..31
            const int obase = 248 - 8 * cch;     // out offset of t = 8c+7 .. 8c
            float sreg[8][NC];
            #pragma unroll
            for (int u = 0; u < 8; ++u)
                #pragma unroll
                for (int i = 0; i < NC; ++i)
                    sreg[u][i] = st_g[(8 * cch + u) * NODE + col[i]];
            #pragma unroll
            for (int i = 0; i < NC; ++i) {
                size_t base = ((size_t)m * NODE + col[i]) * TT + obase;
                *(float4*)(outx + base)     = make_float4(xreg[7][i], xreg[6][i], xreg[5][i], xreg[4][i]);
                *(float4*)(outx + base + 4) = make_float4(xreg[3][i], xreg[2][i], xreg[1][i], xreg[0][i]);
                *(float4*)(outm + base)     = make_float4(mreg[7][i], mreg[6][i], mreg[5][i], mreg[4][i]);
                *(float4*)(outm + base + 4) = make_float4(mreg[3][i], mreg[2][i], mreg[1][i], mreg[0][i]);
                *(float4*)(outs + base)     = make_float4(sreg[7][i], sreg[6][i], sreg[5][i], sreg[4][i]);
                *(float4*)(outs + base + 4) = make_float4(sreg[3][i], sreg[2][i], sreg[1][i], sreg[0][i]);
            }
        }
    }
}

extern "C" void kernel_launch(void* const* d_in, const int* in_sizes, int n_in,
                              void* d_out, int out_size) {
    const float* W    = (const float*)d_in[0];   // (T, NODE, NODE)
    const float* b    = (const float*)d_in[1];   // (T, NODE)
    const float* ne   = (const float*)d_in[2];   // (1, NODE, T)
    const float* eps0 = (const float*)d_in[3];   // (M, NODE)
    const float* eps  = (const float*)d_in[4];   // (T-1, M, NODE)
    float* out = (float*)d_out;                  // [x | m | s], each (M, NODE, T)

    k_softplus<<<(TT * NODE + 255) / 256, 256>>>(ne);
    k_chain<<<MM / RB, NTHREADS>>>(W, b, eps0, eps, out);
}